// round 9
// baseline (speedup 1.0000x reference)
#include <cuda_runtime.h>
#include <cstdint>

typedef unsigned long long u64;

#define Bn   16
#define R    360
#define RPAD 384   // padded row length (float2 units) for u/v scratch

// Scratch: u2[b][dpair k][i] = (u[i][2k], u[i][2k+1]) packed fp32x2; same for v (v includes +b_out)
// __device__ globals are zero-initialized; pad [360,384) stays zero (k1 never writes it).
__device__ u64 g_u2[Bn * 32 * RPAD];
__device__ u64 g_v2[Bn * 32 * RPAD];

// ---------- packed fp32x2 helpers (sm_100+) ----------
__device__ __forceinline__ u64 pack2(float x, float y) {
    u64 d; asm("mov.b64 %0, {%1, %2};" : "=l"(d) : "f"(x), "f"(y)); return d;
}
__device__ __forceinline__ void unpack2(u64 a, float &x, float &y) {
    asm("mov.b64 {%0, %1}, %2;" : "=f"(x), "=f"(y) : "l"(a));
}
__device__ __forceinline__ void ffma2(u64 &d, u64 a, u64 b) {
    asm("fma.rn.f32x2 %0, %1, %2, %0;" : "+l"(d) : "l"(a), "l"(b));
}
// acc += w * relu(u+v)
__device__ __forceinline__ void relu_dot2(u64 &acc, u64 u, u64 v, u64 w) {
    u64 s;
    asm("add.rn.f32x2 %0, %1, %2;" : "=l"(s) : "l"(u), "l"(v));
    float lo, hi; unpack2(s, lo, hi);
    lo = fmaxf(lo, 0.0f); hi = fmaxf(hi, 0.0f);
    s = pack2(lo, hi);
    ffma2(acc, s, w);
}

// ============================================================================
// Kernel 1 (rebuilt): u = x @ Wout[0:64], v = x @ Wout[64:128] + b_out
// 180 blocks x 32 rows. Coalesced x fill (warp sweeps a row's 256B).
// Thread = (row, 16-col group): 512 FFMA2, broadcast W reads.
// ============================================================================
__global__ __launch_bounds__(256, 2) void k1_uv(
    const float* __restrict__ x,      // [5760][64]
    const float* __restrict__ Wout,   // [128][64]
    const float* __restrict__ bout)   // [64]
{
    __shared__ u64 xs[32][33];       // [row][kpair], pad 33 (2-way conflict max)
    __shared__ u64 Wu[32][64];       // [kpair][d]
    __shared__ u64 Wv[32][64];

    const int t = threadIdx.x;
    const int row0 = blockIdx.x * 32;

    // Coalesced x fill: warp w loads rows 4w..4w+3, lane sweeps 32 u64 per row.
    {
        const u64* x2 = (const u64*)x;   // float2 view (32 per row)
        const int w = t >> 5, lane = t & 31;
        #pragma unroll
        for (int rr = 0; rr < 4; rr++) {
            const int r = 4 * w + rr;
            xs[r][lane] = x2[(size_t)(row0 + r) * 32 + lane];
        }
    }
    // Fill Wu / Wv (coalesced on d)
    {
        const int c = t & 63, p0 = t >> 6;
        #pragma unroll
        for (int p = p0; p < 32; p += 4) {
            Wu[p][c] = pack2(Wout[(2 * p) * 64 + c],      Wout[(2 * p + 1) * 64 + c]);
            Wv[p][c] = pack2(Wout[(64 + 2 * p) * 64 + c], Wout[(65 + 2 * p) * 64 + c]);
        }
    }
    __syncthreads();

    const int row = t & 31;           // one row per thread (warp = col group)
    const int g   = t >> 5;           // 0..7: g<4 -> u cols, g>=4 -> v cols
    const int ccol = (g & 3) * 16;    // 16 columns per thread within the half
    const bool isv = (g >= 4);
    const u64 (*Ws)[64] = isv ? Wv : Wu;

    u64 acc[16];
    #pragma unroll
    for (int j = 0; j < 16; j++) acc[j] = 0ull;

    #pragma unroll 4
    for (int p = 0; p < 32; p++) {
        const u64 xv = xs[row][p];            // LDS.64, 2-way conflict max
        #pragma unroll
        for (int q = 0; q < 8; q++) {         // 8x broadcast LDS.128
            ulonglong2 w2 = *(const ulonglong2*)&Ws[p][ccol + 2 * q];
            ffma2(acc[2 * q],     xv, w2.x);  // lo: even-k partial, hi: odd-k
            ffma2(acc[2 * q + 1], xv, w2.y);
        }
    }

    // Epilogue: reduce lo+hi, add b_out for v-half, store transposed pairs.
    // For fixed j, lanes (=rows) of a warp store consecutive i -> coalesced.
    const int grow = row0 + row;
    const int bb = grow / 360;
    const int i = grow - bb * 360;
    u64* gdst = isv ? g_v2 : g_u2;
    #pragma unroll
    for (int j = 0; j < 16; j += 2) {
        float l0, h0, l1, h1;
        unpack2(acc[j],     l0, h0);
        unpack2(acc[j + 1], l1, h1);
        float v0 = l0 + h0, v1 = l1 + h1;
        const int dd = ccol + j;
        if (isv) { v0 += __ldg(&bout[dd]); v1 += __ldg(&bout[dd + 1]); }
        gdst[(bb * 32 + (dd >> 1)) * RPAD + i] = pack2(v0, v1);
    }
}

// ============================================================================
// Kernel 2 (R7-proven, best known: 18.4us): 64x64 tile, 2 sends x 8 recs/thread.
// ============================================================================
__global__ __launch_bounds__(256, 4) void k2_pair(
    const float* __restrict__ Wcat,   // [64]
    const float* __restrict__ bcat,   // [1]
    float* __restrict__ out)          // [16*360*360]
{
    __shared__ u64 Us[32][64];    // [dpair][send]
    __shared__ u64 Vs[32][64];    // [dpair][rec]
    __shared__ u64 Ww[32];        // packed Wcat pairs

    const int t = threadIdx.x;
    const int b  = blockIdx.z;
    const int s0 = blockIdx.x * 64;
    const int r0 = blockIdx.y * 64;

    // Fill tiles (coalesced 512B rows; pad region reads zeros)
    {
        const int c = t & 63, k0 = t >> 6;
        const u64* gu = g_u2 + b * 32 * RPAD + s0 + c;
        const u64* gv = g_v2 + b * 32 * RPAD + r0 + c;
        #pragma unroll
        for (int k = k0; k < 32; k += 4) {
            Us[k][c] = gu[k * RPAD];
            Vs[k][c] = gv[k * RPAD];
        }
        if (t < 32) Ww[t] = ((const u64*)Wcat)[t];
    }
    __syncthreads();

    const int lane = t & 31;       // sends 2*lane, 2*lane+1 (conflict-free LDS.128)
    const int wg   = t >> 5;       // recs 8*wg .. 8*wg+7 (broadcast LDS.128)

    u64 acc[8][2];
    #pragma unroll
    for (int i = 0; i < 8; i++) { acc[i][0] = 0ull; acc[i][1] = 0ull; }

    #pragma unroll 8
    for (int k = 0; k < 32; k++) {
        const u64 w2 = Ww[k];                           // broadcast LDS.64
        ulonglong2 ua = *(const ulonglong2*)&Us[k][2 * lane];   // conflict-free LDS.128
        u64 vv[8];
        #pragma unroll
        for (int q = 0; q < 4; q++) {                   // broadcast LDS.128 x4
            ulonglong2 va = *(const ulonglong2*)&Vs[k][8 * wg + 2 * q];
            vv[2 * q] = va.x; vv[2 * q + 1] = va.y;
        }
        #pragma unroll
        for (int i = 0; i < 8; i++) {
            relu_dot2(acc[i][0], ua.x, vv[i], w2);
            relu_dot2(acc[i][1], ua.y, vv[i], w2);
        }
    }

    // Epilogue: lo+hi + b_cat, relu, float2 stores (256B coalesced per rec row)
    const float bc = __ldg(bcat);
    const int s = s0 + 2 * lane;
    if (s < R) {
        #pragma unroll
        for (int i = 0; i < 8; i++) {
            const int rec = r0 + 8 * wg + i;
            if (rec < R) {
                float l0, h0, l1, h1;
                unpack2(acc[i][0], l0, h0);
                unpack2(acc[i][1], l1, h1);
                float2 o;
                o.x = fmaxf(l0 + h0 + bc, 0.0f);
                o.y = fmaxf(l1 + h1 + bc, 0.0f);
                *(float2*)&out[((size_t)(b * R + rec)) * R + s] = o;
            }
        }
    }
}

extern "C" void kernel_launch(void* const* d_in, const int* in_sizes, int n_in,
                              void* d_out, int out_size) {
    (void)in_sizes; (void)n_in; (void)out_size;
    const float* x    = (const float*)d_in[0];  // (16,360,64)
    const float* Wout = (const float*)d_in[1];  // (128,64)
    const float* bout = (const float*)d_in[2];  // (64)
    const float* Wcat = (const float*)d_in[3];  // (64,1)
    const float* bcat = (const float*)d_in[4];  // (1)
    float* out = (float*)d_out;                 // (16,360,360,1) fp32

    k1_uv<<<180, 256>>>(x, Wout, bout);                   // 5760 rows / 32
    k2_pair<<<dim3(6, 6, 16), 256>>>(Wcat, bcat, out);    // 6 send x 6 rec x 16 batch
}

// round 10
// speedup vs baseline: 1.1315x; 1.1315x over previous
#include <cuda_runtime.h>
#include <cstdint>

typedef unsigned long long u64;

#define Bn   16
#define R    360
#define RPAD 384   // padded row length (float2 units) for u/v scratch

// Scratch: u2[b][dpair k][i] = (u[i][2k], u[i][2k+1]) packed fp32x2; same for v (v includes +b_out)
// __device__ globals are zero-initialized; pad [360,384) stays zero (k1 never writes it).
__device__ u64 g_u2[Bn * 32 * RPAD];
__device__ u64 g_v2[Bn * 32 * RPAD];

// ---------- packed fp32x2 helpers (sm_100+) ----------
__device__ __forceinline__ u64 pack2(float x, float y) {
    u64 d; asm("mov.b64 %0, {%1, %2};" : "=l"(d) : "f"(x), "f"(y)); return d;
}
__device__ __forceinline__ void unpack2(u64 a, float &x, float &y) {
    asm("mov.b64 {%0, %1}, %2;" : "=f"(x), "=f"(y) : "l"(a));
}
__device__ __forceinline__ void ffma2(u64 &d, u64 a, u64 b) {
    asm("fma.rn.f32x2 %0, %1, %2, %0;" : "+l"(d) : "l"(a), "l"(b));
}
// acc += w * relu(u+v)
__device__ __forceinline__ void relu_dot2(u64 &acc, u64 u, u64 v, u64 w) {
    u64 s;
    asm("add.rn.f32x2 %0, %1, %2;" : "=l"(s) : "l"(u), "l"(v));
    float lo, hi; unpack2(s, lo, hi);
    lo = fmaxf(lo, 0.0f); hi = fmaxf(hi, 0.0f);
    s = pack2(lo, hi);
    ffma2(acc, s, w);
}

// ============================================================================
// Kernel 1: u = x @ Wout[0:64], v = x @ Wout[64:128] + b_out
// 360 blocks x 16 rows, 3 CTAs/SM -> single co-resident wave across the chip.
// Thread = (row, 8-col group): 4 u64 accs, 224 hot instrs, coalesced fills.
// ============================================================================
__global__ __launch_bounds__(256, 3) void k1_uv(
    const float* __restrict__ x,      // [5760][64]
    const float* __restrict__ Wout,   // [128][64]
    const float* __restrict__ bout)   // [64]
{
    __shared__ u64 xs[16][33];       // [row][kpair], pad 33
    __shared__ u64 Wu[32][64];       // [kpair][d]
    __shared__ u64 Wv[32][64];

    const int t = threadIdx.x;
    const int row0 = blockIdx.x * 16;

    // Fill Wu / Wv (coalesced on d; W is L2-resident across all 360 blocks)
    {
        const int c = t & 63, p0 = t >> 6;
        #pragma unroll
        for (int p = p0; p < 32; p += 4) {
            Wu[p][c] = pack2(Wout[(2 * p) * 64 + c],      Wout[(2 * p + 1) * 64 + c]);
            Wv[p][c] = pack2(Wout[(64 + 2 * p) * 64 + c], Wout[(65 + 2 * p) * 64 + c]);
        }
    }
    // Coalesced x fill: 512 u64, 2 per thread, 256B per 32-thread sweep
    {
        const u64* x2 = (const u64*)x;   // float2 view (32 per row)
        #pragma unroll
        for (int idx = t; idx < 16 * 32; idx += 256) {
            const int r = idx >> 5, lane = idx & 31;
            xs[r][lane] = x2[(size_t)(row0 + r) * 32 + lane];
        }
    }
    __syncthreads();

    const int row  = t & 15;          // lanes 0-15 rows, lanes 16-31 same rows (bcast)
    const int g    = t >> 4;          // 0..15: g<8 -> u, g>=8 -> v
    const int ccol = (g & 7) * 8;     // 8 cols = 4 pairs per thread
    const bool isv = (g >= 8);
    const u64 (*Ws)[64] = isv ? Wv : Wu;

    u64 acc[4];
    acc[0] = acc[1] = acc[2] = acc[3] = 0ull;

    #pragma unroll
    for (int p = 0; p < 32; p++) {
        const u64 xv = xs[row][p];                          // conflict-free + bcast
        ulonglong2 wa = *(const ulonglong2*)&Ws[p][ccol];   // bcast LDS.128
        ulonglong2 wb = *(const ulonglong2*)&Ws[p][ccol + 2];
        ffma2(acc[0], xv, wa.x);   // lo: even-k partial, hi: odd-k partial
        ffma2(acc[1], xv, wa.y);
        ffma2(acc[2], xv, wb.x);
        ffma2(acc[3], xv, wb.y);
    }

    // Epilogue: reduce lo+hi, add b_out for v-half, store transposed pairs
    const int grow = row0 + row;          // [0, 5760)
    const int bb = grow / 360;
    const int i = grow - bb * 360;
    u64* gdst = isv ? g_v2 : g_u2;
    #pragma unroll
    for (int j = 0; j < 4; j += 2) {
        float l0, h0, l1, h1;
        unpack2(acc[j],     l0, h0);
        unpack2(acc[j + 1], l1, h1);
        float v0 = l0 + h0, v1 = l1 + h1;
        const int dd = ccol + 2 * j;
        if (isv) { v0 += __ldg(&bout[dd]); v1 += __ldg(&bout[dd + 2]); }
        // acc[j] covers d=ccol+2j (pair dp=(ccol+2j)>>1), acc[j+1] -> dp+1
        gdst[(bb * 32 + ((ccol + 2 * j) >> 1)) * RPAD + i]     = pack2(v0, 0.0f);
        gdst[(bb * 32 + ((ccol + 2 * j + 2) >> 1)) * RPAD + i] = pack2(v1, 0.0f);
    }
    // NOTE: the two lines above are wrong pairing — fixed below by proper pairing:
}

// Corrected k1 epilogue requires acc[j] = d-pair (2 adjacent d's), which the
// column mapping above already gives: acc[q] accumulates (even-k, odd-k) partials
// for column ccol+q... To avoid subtle pairing bugs we use a dedicated kernel:
__global__ __launch_bounds__(256, 3) void k1_uv_fixed(
    const float* __restrict__ x,
    const float* __restrict__ Wout,
    const float* __restrict__ bout)
{
    __shared__ u64 xs[16][33];
    __shared__ u64 Wu[32][64];
    __shared__ u64 Wv[32][64];

    const int t = threadIdx.x;
    const int row0 = blockIdx.x * 16;

    {
        const int c = t & 63, p0 = t >> 6;
        #pragma unroll
        for (int p = p0; p < 32; p += 4) {
            Wu[p][c] = pack2(Wout[(2 * p) * 64 + c],      Wout[(2 * p + 1) * 64 + c]);
            Wv[p][c] = pack2(Wout[(64 + 2 * p) * 64 + c], Wout[(65 + 2 * p) * 64 + c]);
        }
    }
    {
        const u64* x2 = (const u64*)x;
        #pragma unroll
        for (int idx = t; idx < 16 * 32; idx += 256) {
            const int r = idx >> 5, lane = idx & 31;
            xs[r][lane] = x2[(size_t)(row0 + r) * 32 + lane];
        }
    }
    __syncthreads();

    const int row  = t & 15;
    const int g    = t >> 4;
    const int ccol = (g & 7) * 8;     // columns ccol..ccol+7
    const bool isv = (g >= 8);
    const u64 (*Ws)[64] = isv ? Wv : Wu;

    u64 acc[8];                        // one per column (lo=even-k, hi=odd-k)
    #pragma unroll
    for (int j = 0; j < 8; j++) acc[j] = 0ull;

    #pragma unroll
    for (int p = 0; p < 32; p++) {
        const u64 xv = xs[row][p];
        ulonglong2 wa = *(const ulonglong2*)&Ws[p][ccol];
        ulonglong2 wb = *(const ulonglong2*)&Ws[p][ccol + 2];
        ulonglong2 wc = *(const ulonglong2*)&Ws[p][ccol + 4];
        ulonglong2 wd = *(const ulonglong2*)&Ws[p][ccol + 6];
        ffma2(acc[0], xv, wa.x);  ffma2(acc[1], xv, wa.y);
        ffma2(acc[2], xv, wb.x);  ffma2(acc[3], xv, wb.y);
        ffma2(acc[4], xv, wc.x);  ffma2(acc[5], xv, wc.y);
        ffma2(acc[6], xv, wd.x);  ffma2(acc[7], xv, wd.y);
    }

    const int grow = row0 + row;
    const int bb = grow / 360;
    const int i = grow - bb * 360;
    u64* gdst = isv ? g_v2 : g_u2;
    #pragma unroll
    for (int j = 0; j < 8; j += 2) {
        float l0, h0, l1, h1;
        unpack2(acc[j],     l0, h0);
        unpack2(acc[j + 1], l1, h1);
        float v0 = l0 + h0, v1 = l1 + h1;      // d = ccol+j, ccol+j+1 (adjacent pair)
        const int dd = ccol + j;
        if (isv) { v0 += __ldg(&bout[dd]); v1 += __ldg(&bout[dd + 1]); }
        gdst[(bb * 32 + (dd >> 1)) * RPAD + i] = pack2(v0, v1);
    }
}

// ============================================================================
// Kernel 2 (R7-proven best, 18.4us): 64x64 tile, 2 sends x 8 recs per thread.
// ============================================================================
__global__ __launch_bounds__(256, 4) void k2_pair(
    const float* __restrict__ Wcat,   // [64]
    const float* __restrict__ bcat,   // [1]
    float* __restrict__ out)          // [16*360*360]
{
    __shared__ u64 Us[32][64];    // [dpair][send]
    __shared__ u64 Vs[32][64];    // [dpair][rec]
    __shared__ u64 Ww[32];        // packed Wcat pairs

    const int t = threadIdx.x;
    const int b  = blockIdx.z;
    const int s0 = blockIdx.x * 64;
    const int r0 = blockIdx.y * 64;

    {
        const int c = t & 63, k0 = t >> 6;
        const u64* gu = g_u2 + b * 32 * RPAD + s0 + c;
        const u64* gv = g_v2 + b * 32 * RPAD + r0 + c;
        #pragma unroll
        for (int k = k0; k < 32; k += 4) {
            Us[k][c] = gu[k * RPAD];
            Vs[k][c] = gv[k * RPAD];
        }
        if (t < 32) Ww[t] = ((const u64*)Wcat)[t];
    }
    __syncthreads();

    const int lane = t & 31;       // sends 2*lane, 2*lane+1 (conflict-free LDS.128)
    const int wg   = t >> 5;       // recs 8*wg .. 8*wg+7 (broadcast LDS.128)

    u64 acc[8][2];
    #pragma unroll
    for (int i = 0; i < 8; i++) { acc[i][0] = 0ull; acc[i][1] = 0ull; }

    #pragma unroll 8
    for (int k = 0; k < 32; k++) {
        const u64 w2 = Ww[k];
        ulonglong2 ua = *(const ulonglong2*)&Us[k][2 * lane];
        u64 vv[8];
        #pragma unroll
        for (int q = 0; q < 4; q++) {
            ulonglong2 va = *(const ulonglong2*)&Vs[k][8 * wg + 2 * q];
            vv[2 * q] = va.x; vv[2 * q + 1] = va.y;
        }
        #pragma unroll
        for (int i = 0; i < 8; i++) {
            relu_dot2(acc[i][0], ua.x, vv[i], w2);
            relu_dot2(acc[i][1], ua.y, vv[i], w2);
        }
    }

    const float bc = __ldg(bcat);
    const int s = s0 + 2 * lane;
    if (s < R) {
        #pragma unroll
        for (int i = 0; i < 8; i++) {
            const int rec = r0 + 8 * wg + i;
            if (rec < R) {
                float l0, h0, l1, h1;
                unpack2(acc[i][0], l0, h0);
                unpack2(acc[i][1], l1, h1);
                float2 o;
                o.x = fmaxf(l0 + h0 + bc, 0.0f);
                o.y = fmaxf(l1 + h1 + bc, 0.0f);
                *(float2*)&out[((size_t)(b * R + rec)) * R + s] = o;
            }
        }
    }
}

extern "C" void kernel_launch(void* const* d_in, const int* in_sizes, int n_in,
                              void* d_out, int out_size) {
    (void)in_sizes; (void)n_in; (void)out_size;
    const float* x    = (const float*)d_in[0];  // (16,360,64)
    const float* Wout = (const float*)d_in[1];  // (128,64)
    const float* bout = (const float*)d_in[2];  // (64)
    const float* Wcat = (const float*)d_in[3];  // (64,1)
    const float* bcat = (const float*)d_in[4];  // (1)
    float* out = (float*)d_out;                 // (16,360,360,1) fp32

    k1_uv_fixed<<<360, 256>>>(x, Wout, bout);             // 5760 rows / 16
    k2_pair<<<dim3(6, 6, 16), 256>>>(Wcat, bcat, out);    // 6 send x 6 rec x 16 batch
}